// round 2
// baseline (speedup 1.0000x reference)
#include <cuda_runtime.h>
#include <cstdint>

#define H 320
#define W 960
#define HW (H * W)

// Scratch (allocation-free: __device__ globals)
__device__ float g_yL[HW], g_yR[HW];
__device__ float g_cbL[HW], g_cbR[HW];
__device__ float g_crL[HW], g_crR[HW];
__device__ unsigned g_cL[HW], g_cR[HW];

__global__ void ycbcr_kernel(const float* __restrict__ left,
                             const float* __restrict__ right) {
    int i = blockIdx.x * blockDim.x + threadIdx.x;
    if (i >= HW) return;
    {
        float r = left[i], g = left[HW + i], b = left[2 * HW + i];
        float y = 0.299f * r + 0.587f * g + 0.114f * b;
        g_yL[i]  = y;
        g_cbL[i] = (b - y) * 0.564f + 0.5f;
        g_crL[i] = (r - y) * 0.713f + 0.5f;
    }
    {
        float r = right[i], g = right[HW + i], b = right[2 * HW + i];
        float y = 0.299f * r + 0.587f * g + 0.114f * b;
        g_yR[i]  = y;
        g_cbR[i] = (b - y) * 0.564f + 0.5f;
        g_crR[i] = (r - y) * 0.713f + 0.5f;
    }
}

__global__ void census_kernel() {
    int i = blockIdx.x * blockDim.x + threadIdx.x;
    if (i >= 2 * HW) return;
    const float* Y = (i < HW) ? g_yL : g_yR;
    unsigned*    C = (i < HW) ? g_cL : g_cR;
    int p = (i < HW) ? i : i - HW;
    int y = p / W;
    int x = p - y * W;
    unsigned cen = 0u;
    if (y >= 2 && y < H - 2 && x >= 2 && x < W - 2) {
        float c = Y[p];
        #pragma unroll
        for (int v = 0; v < 5; v++) {
            #pragma unroll
            for (int u = 0; u < 5; u++) {
                if (v == 1 && u == 1) continue;  // reference skips (v=1,u=1), NOT the center
                cen = (cen << 1) | (Y[(y + v - 2) * W + (x + u - 2)] >= c ? 1u : 0u);
            }
        }
    }
    C[p] = cen;
}

// One block per (d, y). Lanes 0..239 each produce 4 consecutive x for the
// three channel groups (hamming, |dCb|, |dCr|) as float4 stores.
// blockIdx.x = d (fastest) -> consecutive blocks share row y, left-row reads
// stay hot in L2.
__global__ __launch_bounds__(256) void volume_kernel(float* __restrict__ out,
                                                     int maxdisp) {
    int d = blockIdx.x;
    int y = blockIdx.y;
    int lane = threadIdx.x;
    if (lane >= W / 4) return;
    int x = lane * 4;
    int rbase = y * W + x;

    uint4  c4  = *reinterpret_cast<const uint4*>(&g_cR[rbase]);
    float4 cb4 = *reinterpret_cast<const float4*>(&g_cbR[rbase]);
    float4 cr4 = *reinterpret_cast<const float4*>(&g_crR[rbase]);
    unsigned cR[4] = {c4.x, c4.y, c4.z, c4.w};
    float cbR[4]   = {cb4.x, cb4.y, cb4.z, cb4.w};
    float crR[4]   = {cr4.x, cr4.y, cr4.z, cr4.w};

    float ham[4], dcb[4], dcr[4];
    #pragma unroll
    for (int j = 0; j < 4; j++) {
        int xx = x + j + d;
        if (xx < W) {
            int li = y * W + xx;
            ham[j] = (float)__popc(__ldg(&g_cL[li]) ^ cR[j]);
            dcb[j] = fabsf(__ldg(&g_cbL[li]) - cbR[j]);
            dcr[j] = fabsf(__ldg(&g_crL[li]) - crR[j]);
        } else {
            ham[j] = 0.0f; dcb[j] = 0.0f; dcr[j] = 0.0f;
        }
    }

    size_t stride = (size_t)maxdisp * HW;
    size_t o = ((size_t)d * H + y) * W + x;
    *reinterpret_cast<float4*>(&out[o])              = make_float4(ham[0], ham[1], ham[2], ham[3]);
    *reinterpret_cast<float4*>(&out[o + stride])     = make_float4(dcb[0], dcb[1], dcb[2], dcb[3]);
    *reinterpret_cast<float4*>(&out[o + 2 * stride]) = make_float4(dcr[0], dcr[1], dcr[2], dcr[3]);
}

extern "C" void kernel_launch(void* const* d_in, const int* in_sizes, int n_in,
                              void* d_out, int out_size) {
    const float* left  = (const float*)d_in[0];
    const float* right = (const float*)d_in[1];
    float* out = (float*)d_out;
    // maxdisp lives in device memory (d_in[2]); derive it host-side from out_size.
    int maxdisp = out_size / (3 * HW);   // = 128 for the bench shape

    ycbcr_kernel<<<(HW + 255) / 256, 256>>>(left, right);
    census_kernel<<<(2 * HW + 255) / 256, 256>>>();
    dim3 grid(maxdisp, H);
    volume_kernel<<<grid, 256>>>(out, maxdisp);
}

// round 3
// speedup vs baseline: 1.0013x; 1.0013x over previous
#include <cuda_runtime.h>
#include <cstdint>

#define H 320
#define W 960
#define HW (H * W)

// Scratch (allocation-free: __device__ globals)
__device__ float g_yL[HW], g_yR[HW];
__device__ float g_cbL[HW], g_cbR[HW];
__device__ float g_crL[HW], g_crR[HW];
__device__ unsigned g_cL[HW], g_cR[HW];

__global__ void ycbcr_kernel(const float* __restrict__ left,
                             const float* __restrict__ right) {
    int i = blockIdx.x * blockDim.x + threadIdx.x;
    if (i >= HW) return;
    {
        float r = left[i], g = left[HW + i], b = left[2 * HW + i];
        float y = 0.299f * r + 0.587f * g + 0.114f * b;
        g_yL[i]  = y;
        g_cbL[i] = (b - y) * 0.564f + 0.5f;
        g_crL[i] = (r - y) * 0.713f + 0.5f;
    }
    {
        float r = right[i], g = right[HW + i], b = right[2 * HW + i];
        float y = 0.299f * r + 0.587f * g + 0.114f * b;
        g_yR[i]  = y;
        g_cbR[i] = (b - y) * 0.564f + 0.5f;
        g_crR[i] = (r - y) * 0.713f + 0.5f;
    }
}

__global__ void census_kernel() {
    int i = blockIdx.x * blockDim.x + threadIdx.x;
    if (i >= 2 * HW) return;
    const float* Y = (i < HW) ? g_yL : g_yR;
    unsigned*    C = (i < HW) ? g_cL : g_cR;
    int p = (i < HW) ? i : i - HW;
    int y = p / W;
    int x = p - y * W;
    unsigned cen = 0u;
    if (y >= 2 && y < H - 2 && x >= 2 && x < W - 2) {
        float c = Y[p];
        #pragma unroll
        for (int v = 0; v < 5; v++) {
            #pragma unroll
            for (int u = 0; u < 5; u++) {
                if (v == 1 && u == 1) continue;  // reference skips (v=1,u=1), NOT the center
                cen = (cen << 1) | (Y[(y + v - 2) * W + (x + u - 2)] >= c ? 1u : 0u);
            }
        }
    }
    C[p] = cen;
}

// One block per (d, y). Lanes 0..239 each produce 4 consecutive x for the
// three channel groups (hamming, |dCb|, |dCr|) as float4 stores.
// blockIdx.x = d (fastest) -> consecutive blocks share row y, left-row reads
// stay hot in L2.
__global__ __launch_bounds__(256) void volume_kernel(float* __restrict__ out,
                                                     int maxdisp) {
    int d = blockIdx.x;
    int y = blockIdx.y;
    int lane = threadIdx.x;
    if (lane >= W / 4) return;
    int x = lane * 4;
    int rbase = y * W + x;

    uint4  c4  = *reinterpret_cast<const uint4*>(&g_cR[rbase]);
    float4 cb4 = *reinterpret_cast<const float4*>(&g_cbR[rbase]);
    float4 cr4 = *reinterpret_cast<const float4*>(&g_crR[rbase]);
    unsigned cR[4] = {c4.x, c4.y, c4.z, c4.w};
    float cbR[4]   = {cb4.x, cb4.y, cb4.z, cb4.w};
    float crR[4]   = {cr4.x, cr4.y, cr4.z, cr4.w};

    float ham[4], dcb[4], dcr[4];
    #pragma unroll
    for (int j = 0; j < 4; j++) {
        int xx = x + j + d;
        if (xx < W) {
            int li = y * W + xx;
            ham[j] = (float)__popc(__ldg(&g_cL[li]) ^ cR[j]);
            dcb[j] = fabsf(__ldg(&g_cbL[li]) - cbR[j]);
            dcr[j] = fabsf(__ldg(&g_crL[li]) - crR[j]);
        } else {
            ham[j] = 0.0f; dcb[j] = 0.0f; dcr[j] = 0.0f;
        }
    }

    size_t stride = (size_t)maxdisp * HW;
    size_t o = ((size_t)d * H + y) * W + x;
    *reinterpret_cast<float4*>(&out[o])              = make_float4(ham[0], ham[1], ham[2], ham[3]);
    *reinterpret_cast<float4*>(&out[o + stride])     = make_float4(dcb[0], dcb[1], dcb[2], dcb[3]);
    *reinterpret_cast<float4*>(&out[o + 2 * stride]) = make_float4(dcr[0], dcr[1], dcr[2], dcr[3]);
}

extern "C" void kernel_launch(void* const* d_in, const int* in_sizes, int n_in,
                              void* d_out, int out_size) {
    const float* left  = (const float*)d_in[0];
    const float* right = (const float*)d_in[1];
    float* out = (float*)d_out;
    // maxdisp lives in device memory (d_in[2]); derive it host-side from out_size.
    int maxdisp = out_size / (3 * HW);   // = 128 for the bench shape

    ycbcr_kernel<<<(HW + 255) / 256, 256>>>(left, right);
    census_kernel<<<(2 * HW + 255) / 256, 256>>>();
    dim3 grid(maxdisp, H);
    volume_kernel<<<grid, 256>>>(out, maxdisp);
}

// round 5
// speedup vs baseline: 1.1977x; 1.1961x over previous
#include <cuda_runtime.h>
#include <cstdint>

#define H 320
#define W 960
#define HW (H * W)

// Scratch (allocation-free: __device__ globals)
__device__ float g_yL[HW], g_yR[HW];
__device__ float g_cbL[HW], g_cbR[HW];
__device__ float g_crL[HW], g_crR[HW];
__device__ unsigned g_cL[HW], g_cR[HW];

__global__ void ycbcr_kernel(const float* __restrict__ left,
                             const float* __restrict__ right) {
    int i = blockIdx.x * blockDim.x + threadIdx.x;
    if (i >= HW) return;
    {
        float r = left[i], g = left[HW + i], b = left[2 * HW + i];
        float y = 0.299f * r + 0.587f * g + 0.114f * b;
        g_yL[i]  = y;
        g_cbL[i] = (b - y) * 0.564f + 0.5f;
        g_crL[i] = (r - y) * 0.713f + 0.5f;
    }
    {
        float r = right[i], g = right[HW + i], b = right[2 * HW + i];
        float y = 0.299f * r + 0.587f * g + 0.114f * b;
        g_yR[i]  = y;
        g_cbR[i] = (b - y) * 0.564f + 0.5f;
        g_crR[i] = (r - y) * 0.713f + 0.5f;
    }
}

__global__ void census_kernel() {
    int i = blockIdx.x * blockDim.x + threadIdx.x;
    if (i >= 2 * HW) return;
    const float* Y = (i < HW) ? g_yL : g_yR;
    unsigned*    C = (i < HW) ? g_cL : g_cR;
    int p = (i < HW) ? i : i - HW;
    int y = p / W;
    int x = p - y * W;
    unsigned cen = 0u;
    if (y >= 2 && y < H - 2 && x >= 2 && x < W - 2) {
        float c = Y[p];
        #pragma unroll
        for (int v = 0; v < 5; v++) {
            #pragma unroll
            for (int u = 0; u < 5; u++) {
                if (v == 1 && u == 1) continue;  // reference skips (v=1,u=1), NOT the center
                cen = (cen << 1) | (Y[(y + v - 2) * W + (x + u - 2)] >= c ? 1u : 0u);
            }
        }
    }
    C[p] = cen;
}

// One block per (d-pair, y). Lanes 0..239 each produce 4 consecutive x for the
// three channel groups (hamming, |dCb|, |dCr|) for TWO disparities.
// blockIdx.x = d-pair (fastest) -> concurrent blocks share row y; left/right
// row reads stay hot in L2. Output stores use .cs (evict-first streaming) so
// the 472MB write stream does NOT evict the ~10MB of intermediates from L2.
__global__ __launch_bounds__(256) void volume_kernel(float* __restrict__ out,
                                                     int maxdisp) {
    int d0 = blockIdx.x * 2;
    int y  = blockIdx.y;
    int lane = threadIdx.x;
    if (lane >= W / 4) return;
    int x = lane * 4;
    int rbase = y * W + x;

    uint4  c4  = *reinterpret_cast<const uint4*>(&g_cR[rbase]);
    float4 cb4 = *reinterpret_cast<const float4*>(&g_cbR[rbase]);
    float4 cr4 = *reinterpret_cast<const float4*>(&g_crR[rbase]);
    unsigned cR[4] = {c4.x, c4.y, c4.z, c4.w};
    float cbR[4]   = {cb4.x, cb4.y, cb4.z, cb4.w};
    float crR[4]   = {cr4.x, cr4.y, cr4.z, cr4.w};

    size_t stride = (size_t)maxdisp * HW;

    #pragma unroll
    for (int dd = 0; dd < 2; dd++) {
        int d = d0 + dd;
        if (d >= maxdisp) break;

        float ham[4], dcb[4], dcr[4];
        #pragma unroll
        for (int j = 0; j < 4; j++) {
            int xx = x + j + d;
            if (xx < W) {
                int li = y * W + xx;
                ham[j] = (float)__popc(__ldg(&g_cL[li]) ^ cR[j]);
                dcb[j] = fabsf(__ldg(&g_cbL[li]) - cbR[j]);
                dcr[j] = fabsf(__ldg(&g_crL[li]) - crR[j]);
            } else {
                ham[j] = 0.0f; dcb[j] = 0.0f; dcr[j] = 0.0f;
            }
        }

        size_t o = ((size_t)d * H + y) * W + x;
        __stcs(reinterpret_cast<float4*>(&out[o]),
               make_float4(ham[0], ham[1], ham[2], ham[3]));
        __stcs(reinterpret_cast<float4*>(&out[o + stride]),
               make_float4(dcb[0], dcb[1], dcb[2], dcb[3]));
        __stcs(reinterpret_cast<float4*>(&out[o + 2 * stride]),
               make_float4(dcr[0], dcr[1], dcr[2], dcr[3]));
    }
}

extern "C" void kernel_launch(void* const* d_in, const int* in_sizes, int n_in,
                              void* d_out, int out_size) {
    const float* left  = (const float*)d_in[0];
    const float* right = (const float*)d_in[1];
    float* out = (float*)d_out;
    // maxdisp lives in device memory (d_in[2]); derive it host-side from out_size.
    int maxdisp = out_size / (3 * HW);   // = 128 for the bench shape

    ycbcr_kernel<<<(HW + 255) / 256, 256>>>(left, right);
    census_kernel<<<(2 * HW + 255) / 256, 256>>>();
    dim3 grid((maxdisp + 1) / 2, H);
    volume_kernel<<<grid, 256>>>(out, maxdisp);
}

// round 6
// speedup vs baseline: 1.2962x; 1.0823x over previous
#include <cuda_runtime.h>
#include <cstdint>

#define H 320
#define W 960
#define HW (H * W)

// Fused prep tile config
#define TX 64
#define TY 8
#define SX (TX + 4)
#define SY (TY + 4)

// Disparities per volume block
#define DPB 4

// Scratch (allocation-free: __device__ globals). Y plane never hits global.
__device__ float g_cbL[HW], g_cbR[HW];
__device__ float g_crL[HW], g_crR[HW];
__device__ unsigned g_cL[HW], g_cR[HW];

// Fused YCbCr + census. One block per 64x8 tile per image (blockIdx.z).
// Y computed into smem (with 2-px halo), census read from smem; cb/cr
// written to global during phase 1.
__global__ __launch_bounds__(256) void prep_kernel(const float* __restrict__ left,
                                                   const float* __restrict__ right) {
    int img = blockIdx.z;
    const float* src = img ? right : left;
    float* cb    = img ? g_cbR : g_cbL;
    float* cr    = img ? g_crR : g_crL;
    unsigned* C  = img ? g_cR  : g_cL;

    __shared__ float sY[SY][SX];
    int tx0 = blockIdx.x * TX, ty0 = blockIdx.y * TY;

    // Phase 1: compute Y for tile+halo into smem; write cb/cr for interior.
    for (int idx = threadIdx.x; idx < SX * SY; idx += 256) {
        int sy = idx / SX, sx = idx - sy * SX;
        int gx = tx0 + sx - 2, gy = ty0 + sy - 2;
        float yv = 0.0f;
        if (gx >= 0 && gx < W && gy >= 0 && gy < H) {
            int p = gy * W + gx;
            float r = src[p], g = src[HW + p], b = src[2 * HW + p];
            yv = 0.299f * r + 0.587f * g + 0.114f * b;
            if (sx >= 2 && sx < SX - 2 && sy >= 2 && sy < SY - 2) {
                cb[p] = (b - yv) * 0.564f + 0.5f;
                cr[p] = (r - yv) * 0.713f + 0.5f;
            }
        }
        sY[sy][sx] = yv;
    }
    __syncthreads();

    // Phase 2: census from smem. 256 threads cover 64x8 tile in 2 passes.
    int px = threadIdx.x % TX;
    for (int py = threadIdx.x / TX; py < TY; py += 256 / TX) {
        int gx = tx0 + px, gy = ty0 + py;
        unsigned cen = 0u;
        if (gx >= 2 && gx < W - 2 && gy >= 2 && gy < H - 2) {
            float c = sY[py + 2][px + 2];
            #pragma unroll
            for (int v = 0; v < 5; v++) {
                #pragma unroll
                for (int u = 0; u < 5; u++) {
                    if (v == 1 && u == 1) continue;  // reference skips (1,1), NOT the center
                    cen = (cen << 1) | (sY[py + v][px + u] >= c ? 1u : 0u);
                }
            }
        }
        C[gy * W + gx] = cen;
    }
}

// One block per (d-group of DPB, y). Lanes 0..239 each produce 4 consecutive x
// for the three channel groups (hamming, |dCb|, |dCr|) for DPB disparities.
// blockIdx.x = d-group (fastest) -> concurrent blocks share row y; left/right
// row reads stay hot in L1/L2, and each block amortizes one row-set read over
// DPB disparities (cuts LTS read traffic). Output stores use .cs (evict-first
// streaming) so the 472MB write stream doesn't evict intermediates from L2.
__global__ __launch_bounds__(256) void volume_kernel(float* __restrict__ out,
                                                     int maxdisp) {
    int d0 = blockIdx.x * DPB;
    int y  = blockIdx.y;
    int lane = threadIdx.x;
    if (lane >= W / 4) return;
    int x = lane * 4;
    int rbase = y * W + x;

    uint4  c4  = *reinterpret_cast<const uint4*>(&g_cR[rbase]);
    float4 cb4 = *reinterpret_cast<const float4*>(&g_cbR[rbase]);
    float4 cr4 = *reinterpret_cast<const float4*>(&g_crR[rbase]);
    unsigned cR[4] = {c4.x, c4.y, c4.z, c4.w};
    float cbR[4]   = {cb4.x, cb4.y, cb4.z, cb4.w};
    float crR[4]   = {cr4.x, cr4.y, cr4.z, cr4.w};

    size_t stride = (size_t)maxdisp * HW;

    #pragma unroll
    for (int dd = 0; dd < DPB; dd++) {
        int d = d0 + dd;
        if (d >= maxdisp) break;

        float ham[4], dcb[4], dcr[4];
        #pragma unroll
        for (int j = 0; j < 4; j++) {
            int xx = x + j + d;
            if (xx < W) {
                int li = y * W + xx;
                ham[j] = (float)__popc(__ldg(&g_cL[li]) ^ cR[j]);
                dcb[j] = fabsf(__ldg(&g_cbL[li]) - cbR[j]);
                dcr[j] = fabsf(__ldg(&g_crL[li]) - crR[j]);
            } else {
                ham[j] = 0.0f; dcb[j] = 0.0f; dcr[j] = 0.0f;
            }
        }

        size_t o = ((size_t)d * H + y) * W + x;
        __stcs(reinterpret_cast<float4*>(&out[o]),
               make_float4(ham[0], ham[1], ham[2], ham[3]));
        __stcs(reinterpret_cast<float4*>(&out[o + stride]),
               make_float4(dcb[0], dcb[1], dcb[2], dcb[3]));
        __stcs(reinterpret_cast<float4*>(&out[o + 2 * stride]),
               make_float4(dcr[0], dcr[1], dcr[2], dcr[3]));
    }
}

extern "C" void kernel_launch(void* const* d_in, const int* in_sizes, int n_in,
                              void* d_out, int out_size) {
    const float* left  = (const float*)d_in[0];
    const float* right = (const float*)d_in[1];
    float* out = (float*)d_out;
    // maxdisp lives in device memory (d_in[2]); derive it host-side from out_size.
    int maxdisp = out_size / (3 * HW);   // = 128 for the bench shape

    dim3 pgrid(W / TX, H / TY, 2);       // 15 x 40 x 2
    prep_kernel<<<pgrid, 256>>>(left, right);

    dim3 vgrid((maxdisp + DPB - 1) / DPB, H);
    volume_kernel<<<vgrid, 256>>>(out, maxdisp);
}

// round 7
// speedup vs baseline: 1.6056x; 1.2387x over previous
#include <cuda_runtime.h>
#include <cstdint>

#define H 320
#define W 960
#define HW (H * W)
#define PAD 128   // slack so left-window vector loads can't run past the array

// Fused prep tile config
#define TX 64
#define TY 8
#define SX (TX + 4)
#define SY (TY + 4)

// Disparities per volume block (must stay multiple of 4 for aligned left loads)
#define DPB 4

// Scratch (allocation-free: __device__ globals). Y plane never hits global.
__device__ float g_cbL[HW + PAD], g_cbR[HW + PAD];
__device__ float g_crL[HW + PAD], g_crR[HW + PAD];
__device__ unsigned g_cL[HW + PAD], g_cR[HW + PAD];

// Fused YCbCr + census. One block per 64x8 tile per image (blockIdx.z).
__global__ __launch_bounds__(256) void prep_kernel(const float* __restrict__ left,
                                                   const float* __restrict__ right) {
    int img = blockIdx.z;
    const float* src = img ? right : left;
    float* cb    = img ? g_cbR : g_cbL;
    float* cr    = img ? g_crR : g_crL;
    unsigned* C  = img ? g_cR  : g_cL;

    __shared__ float sY[SY][SX];
    int tx0 = blockIdx.x * TX, ty0 = blockIdx.y * TY;

    // Phase 1: compute Y for tile+halo into smem; write cb/cr for interior.
    for (int idx = threadIdx.x; idx < SX * SY; idx += 256) {
        int sy = idx / SX, sx = idx - sy * SX;
        int gx = tx0 + sx - 2, gy = ty0 + sy - 2;
        float yv = 0.0f;
        if (gx >= 0 && gx < W && gy >= 0 && gy < H) {
            int p = gy * W + gx;
            float r = src[p], g = src[HW + p], b = src[2 * HW + p];
            yv = 0.299f * r + 0.587f * g + 0.114f * b;
            if (sx >= 2 && sx < SX - 2 && sy >= 2 && sy < SY - 2) {
                cb[p] = (b - yv) * 0.564f + 0.5f;
                cr[p] = (r - yv) * 0.713f + 0.5f;
            }
        }
        sY[sy][sx] = yv;
    }
    __syncthreads();

    // Phase 2: census from smem.
    int px = threadIdx.x % TX;
    for (int py = threadIdx.x / TX; py < TY; py += 256 / TX) {
        int gx = tx0 + px, gy = ty0 + py;
        unsigned cen = 0u;
        if (gx >= 2 && gx < W - 2 && gy >= 2 && gy < H - 2) {
            float c = sY[py + 2][px + 2];
            #pragma unroll
            for (int v = 0; v < 5; v++) {
                #pragma unroll
                for (int u = 0; u < 5; u++) {
                    if (v == 1 && u == 1) continue;  // reference skips (1,1), NOT the center
                    cen = (cen << 1) | (sY[py + v][px + u] >= c ? 1u : 0u);
                }
            }
        }
        C[gy * W + gx] = cen;
    }
}

// One block per (d-group, y). Lanes 0..239 each produce 4 consecutive x for
// three channel groups (hamming, |dCb|, |dCr|) for DPB disparities.
// Left operands: since d0 % 4 == 0, each thread's left window across all DPB
// disparities is left[x+d0 .. x+d0+7] -> two ALIGNED uint4 loads per array;
// per-disparity windows are register selections. This removes the 48 scalar
// misaligned __ldg's per thread that saturated L1 (88.2%).
// Out-of-range lanes read neighbor-row garbage (masked on output; arrays padded).
__global__ __launch_bounds__(256) void volume_kernel(float* __restrict__ out,
                                                     int maxdisp) {
    int d0 = blockIdx.x * DPB;
    int y  = blockIdx.y;
    int lane = threadIdx.x;
    if (lane >= W / 4) return;
    int x = lane * 4;
    int rbase = y * W + x;

    uint4  c4  = *reinterpret_cast<const uint4*>(&g_cR[rbase]);
    float4 cb4 = *reinterpret_cast<const float4*>(&g_cbR[rbase]);
    float4 cr4 = *reinterpret_cast<const float4*>(&g_crR[rbase]);
    unsigned cR[4] = {c4.x, c4.y, c4.z, c4.w};
    float cbR[4]   = {cb4.x, cb4.y, cb4.z, cb4.w};
    float crR[4]   = {cr4.x, cr4.y, cr4.z, cr4.w};

    // Left windows: 8 words per array, 16B-aligned (W%4==0, x%4==0, d0%4==0).
    int lb = rbase + d0;
    uint4 ca = *reinterpret_cast<const uint4*>(&g_cL[lb]);
    uint4 cb_ = *reinterpret_cast<const uint4*>(&g_cL[lb + 4]);
    float4 ba = *reinterpret_cast<const float4*>(&g_cbL[lb]);
    float4 bb = *reinterpret_cast<const float4*>(&g_cbL[lb + 4]);
    float4 ra = *reinterpret_cast<const float4*>(&g_crL[lb]);
    float4 rb = *reinterpret_cast<const float4*>(&g_crL[lb + 4]);
    unsigned cl[8] = {ca.x, ca.y, ca.z, ca.w, cb_.x, cb_.y, cb_.z, cb_.w};
    float    bl[8] = {ba.x, ba.y, ba.z, ba.w, bb.x, bb.y, bb.z, bb.w};
    float    rl[8] = {ra.x, ra.y, ra.z, ra.w, rb.x, rb.y, rb.z, rb.w};

    size_t stride = (size_t)maxdisp * HW;

    #pragma unroll
    for (int dd = 0; dd < DPB; dd++) {
        int d = d0 + dd;
        if (d >= maxdisp) break;

        float ham[4], dcb[4], dcr[4];
        #pragma unroll
        for (int j = 0; j < 4; j++) {
            bool valid = (x + j + d) < W;
            ham[j] = valid ? (float)__popc(cl[dd + j] ^ cR[j]) : 0.0f;
            dcb[j] = valid ? fabsf(bl[dd + j] - cbR[j]) : 0.0f;
            dcr[j] = valid ? fabsf(rl[dd + j] - crR[j]) : 0.0f;
        }

        size_t o = ((size_t)d * H + y) * W + x;
        __stcs(reinterpret_cast<float4*>(&out[o]),
               make_float4(ham[0], ham[1], ham[2], ham[3]));
        __stcs(reinterpret_cast<float4*>(&out[o + stride]),
               make_float4(dcb[0], dcb[1], dcb[2], dcb[3]));
        __stcs(reinterpret_cast<float4*>(&out[o + 2 * stride]),
               make_float4(dcr[0], dcr[1], dcr[2], dcr[3]));
    }
}

extern "C" void kernel_launch(void* const* d_in, const int* in_sizes, int n_in,
                              void* d_out, int out_size) {
    const float* left  = (const float*)d_in[0];
    const float* right = (const float*)d_in[1];
    float* out = (float*)d_out;
    // maxdisp lives in device memory (d_in[2]); derive it host-side from out_size.
    int maxdisp = out_size / (3 * HW);   // = 128 for the bench shape

    dim3 pgrid(W / TX, H / TY, 2);       // 15 x 40 x 2
    prep_kernel<<<pgrid, 256>>>(left, right);

    dim3 vgrid((maxdisp + DPB - 1) / DPB, H);
    volume_kernel<<<vgrid, 256>>>(out, maxdisp);
}

// round 9
// speedup vs baseline: 1.6062x; 1.0004x over previous
#include <cuda_runtime.h>
#include <cstdint>

#define H 320
#define W 960
#define HW (H * W)
#define PAD 128   // slack so left-window vector loads can't run past the array

// Fused prep tile config
#define TX 64
#define TY 8
#define SX (TX + 4)
#define SY (TY + 4)

// Disparities per volume block (multiple of 4 for aligned left loads)
#define DPB 8

// Scratch (allocation-free: __device__ globals). Y plane never hits global.
__device__ float g_cbL[HW + PAD], g_cbR[HW + PAD];
__device__ float g_crL[HW + PAD], g_crR[HW + PAD];
__device__ unsigned g_cL[HW + PAD], g_cR[HW + PAD];

// Fused YCbCr + census. One block per 64x8 tile per image (blockIdx.z).
__global__ __launch_bounds__(256) void prep_kernel(const float* __restrict__ left,
                                                   const float* __restrict__ right) {
    int img = blockIdx.z;
    const float* src = img ? right : left;
    float* cb    = img ? g_cbR : g_cbL;
    float* cr    = img ? g_crR : g_crL;
    unsigned* C  = img ? g_cR  : g_cL;

    __shared__ float sY[SY][SX];
    int tx0 = blockIdx.x * TX, ty0 = blockIdx.y * TY;

    // Phase 1: compute Y for tile+halo into smem; write cb/cr for interior.
    for (int idx = threadIdx.x; idx < SX * SY; idx += 256) {
        int sy = idx / SX, sx = idx - sy * SX;
        int gx = tx0 + sx - 2, gy = ty0 + sy - 2;
        float yv = 0.0f;
        if (gx >= 0 && gx < W && gy >= 0 && gy < H) {
            int p = gy * W + gx;
            float r = src[p], g = src[HW + p], b = src[2 * HW + p];
            yv = 0.299f * r + 0.587f * g + 0.114f * b;
            if (sx >= 2 && sx < SX - 2 && sy >= 2 && sy < SY - 2) {
                cb[p] = (b - yv) * 0.564f + 0.5f;
                cr[p] = (r - yv) * 0.713f + 0.5f;
            }
        }
        sY[sy][sx] = yv;
    }
    __syncthreads();

    // Phase 2: census from smem.
    int px = threadIdx.x % TX;
    for (int py = threadIdx.x / TX; py < TY; py += 256 / TX) {
        int gx = tx0 + px, gy = ty0 + py;
        unsigned cen = 0u;
        if (gx >= 2 && gx < W - 2 && gy >= 2 && gy < H - 2) {
            float c = sY[py + 2][px + 2];
            #pragma unroll
            for (int v = 0; v < 5; v++) {
                #pragma unroll
                for (int u = 0; u < 5; u++) {
                    if (v == 1 && u == 1) continue;  // reference skips (1,1), NOT the center
                    cen = (cen << 1) | (sY[py + v][px + u] >= c ? 1u : 0u);
                }
            }
        }
        C[gy * W + gx] = cen;
    }
}

// One block per (d-group of DPB, y). Lanes 0..239 produce 4 consecutive x for
// three channel groups (hamming, |dCb|, |dCr|) across DPB disparities.
// Left operands: d0 % 4 == 0 -> thread's left window over all DPB disparities
// is left[x+d0 .. x+d0+DPB+3] -> (DPB/4 + 1) ALIGNED vector loads per array;
// per-disparity selection is register shuffling (free under full unroll).
// Loads per thread: 3 right + 9 left = 12 for 3*DPB=24 float4 stores.
// Out-of-range lanes read neighbor-row garbage (masked on output; arrays padded).
__global__ __launch_bounds__(256) void volume_kernel(float* __restrict__ out,
                                                     int maxdisp) {
    int d0 = blockIdx.x * DPB;
    int y  = blockIdx.y;
    int lane = threadIdx.x;
    if (lane >= W / 4) return;
    int x = lane * 4;
    int rbase = y * W + x;

    uint4  c4  = *reinterpret_cast<const uint4*>(&g_cR[rbase]);
    float4 cb4 = *reinterpret_cast<const float4*>(&g_cbR[rbase]);
    float4 cr4 = *reinterpret_cast<const float4*>(&g_crR[rbase]);
    unsigned cR[4] = {c4.x, c4.y, c4.z, c4.w};
    float cbR[4]   = {cb4.x, cb4.y, cb4.z, cb4.w};
    float crR[4]   = {cr4.x, cr4.y, cr4.z, cr4.w};

    // Left windows: DPB+4 = 12 words per array, 16B-aligned.
    int lb = rbase + d0;
    unsigned cl[DPB + 4];
    float    bl[DPB + 4];
    float    rl[DPB + 4];
    #pragma unroll
    for (int g = 0; g < (DPB + 4) / 4; g++) {
        uint4  cv = *reinterpret_cast<const uint4*>(&g_cL[lb + 4 * g]);
        float4 bv = *reinterpret_cast<const float4*>(&g_cbL[lb + 4 * g]);
        float4 rv = *reinterpret_cast<const float4*>(&g_crL[lb + 4 * g]);
        cl[4 * g + 0] = cv.x; cl[4 * g + 1] = cv.y; cl[4 * g + 2] = cv.z; cl[4 * g + 3] = cv.w;
        bl[4 * g + 0] = bv.x; bl[4 * g + 1] = bv.y; bl[4 * g + 2] = bv.z; bl[4 * g + 3] = bv.w;
        rl[4 * g + 0] = rv.x; rl[4 * g + 1] = rv.y; rl[4 * g + 2] = rv.z; rl[4 * g + 3] = rv.w;
    }

    size_t stride = (size_t)maxdisp * HW;
    int rem = W - x - d0;   // lane valid iff dd + j < rem

    #pragma unroll
    for (int dd = 0; dd < DPB; dd++) {
        int d = d0 + dd;

        float ham[4], dcb[4], dcr[4];
        #pragma unroll
        for (int j = 0; j < 4; j++) {
            bool valid = (dd + j) < rem;
            ham[j] = valid ? (float)__popc(cl[dd + j] ^ cR[j]) : 0.0f;
            dcb[j] = valid ? fabsf(bl[dd + j] - cbR[j]) : 0.0f;
            dcr[j] = valid ? fabsf(rl[dd + j] - crR[j]) : 0.0f;
        }

        size_t o = ((size_t)d * H + y) * W + x;
        __stcs(reinterpret_cast<float4*>(&out[o]),
               make_float4(ham[0], ham[1], ham[2], ham[3]));
        __stcs(reinterpret_cast<float4*>(&out[o + stride]),
               make_float4(dcb[0], dcb[1], dcb[2], dcb[3]));
        __stcs(reinterpret_cast<float4*>(&out[o + 2 * stride]),
               make_float4(dcr[0], dcr[1], dcr[2], dcr[3]));
    }
}

extern "C" void kernel_launch(void* const* d_in, const int* in_sizes, int n_in,
                              void* d_out, int out_size) {
    const float* left  = (const float*)d_in[0];
    const float* right = (const float*)d_in[1];
    float* out = (float*)d_out;
    // maxdisp lives in device memory (d_in[2]); derive it host-side from out_size.
    int maxdisp = out_size / (3 * HW);   // = 128 for the bench shape

    dim3 pgrid(W / TX, H / TY, 2);       // 15 x 40 x 2
    prep_kernel<<<pgrid, 256>>>(left, right);

    dim3 vgrid((maxdisp + DPB - 1) / DPB, H);  // maxdisp=128 divisible by DPB=8
    volume_kernel<<<vgrid, 256>>>(out, maxdisp);
}